// round 3
// baseline (speedup 1.0000x reference)
#include <cuda_runtime.h>
#include <math.h>

#define BB   16
#define LL   4096
#define DD   512
#define LP1  4097
#define D4   128        // D / 4 float4 per row
#define CH   8          // l-chunk per recurrence thread (512 blocks)

// Scratch (no allocations allowed): emb table (8 MB, stays L2-resident).
__device__ float g_emb[LL * DD];

// ---------------------------------------------------------------------------
// c[d] = 100^(-(d - d%2)/512) + (pi/2)*(d%2) computed as r^(d>>1) with
// r = 100^(-1/256) via binary exponentiation (pure DMUL, ~2.5e-10 rel err,
// below f32 ulp — matches the reference coefficient after f32 rounding).
// ---------------------------------------------------------------------------
__device__ __forceinline__ float coef(int d) {
    const double R = 0.982171889188039;   // 100^(-1/256)
    double f = 1.0, p = R;
    int k = d >> 1;                        // 0..255
#pragma unroll
    for (int i = 0; i < 8; i++) {
        if (k & 1) f *= p;
        p *= p;
        k >>= 1;
    }
    return (float)f + ((d & 1) ? 1.57079632679489662f : 0.0f);
}

// ---------------------------------------------------------------------------
// Kernel 1: emb[l][d] = sin(l * c[d]) via angle-addition recurrence.
// One thread per d, one block per CH=8 consecutive l values (512 blocks ->
// ~3.5 waves, anchor sincos latency overlapped across waves; dependent
// recurrence chain is only 8 steps).
// ---------------------------------------------------------------------------
__global__ void __launch_bounds__(DD)
compute_emb_kernel() {
    int d  = threadIdx.x;           // 0..511
    int l0 = blockIdx.x * CH;       // 512 blocks
    float c = coef(d);

    float s, cs, sd, cd;
    sincosf((float)l0 * c, &s, &cs);   // exact anchor at chunk start
    sincosf(c, &sd, &cd);              // step rotation

    float* p = &g_emb[l0 * DD + d];
#pragma unroll
    for (int k = 0; k < CH; k++) {
        p[k * DD] = s;
        float ns = fmaf(s,  cd, cs * sd);
        float nc = fmaf(cs, cd, -(s * sd));
        s = ns; cs = nc;
    }
}

// ---------------------------------------------------------------------------
// Kernel 2: stream out[b,l,:] = tokens+emb (l<len) | cls (l==len) | 0 (else).
// 512 threads / block, 8 rows / block, 2 rows per thread -> MLP 4.
// __ldcs on tokens (read-once) and __stcs on output (write-once) keep L2
// free for the emb table, which is re-read 16x (once per batch element).
// ---------------------------------------------------------------------------
__device__ __forceinline__ float4 row_value(const float4* __restrict__ tok,
                                            const float4* __restrict__ cls,
                                            int row, int d4)
{
    int b = row / LP1;
    int l = row - b * LP1;
    // lengths are broadcast via __ldg in caller; recompute here costs a div —
    // instead caller passes len. (kept inline below)
    return make_float4(0.f, 0.f, 0.f, 0.f); // unused; logic inlined in kernel
}

__global__ void __launch_bounds__(512)
stream_kernel(const float4* __restrict__ tok,
              const int*    __restrict__ lengths,
              const float4* __restrict__ cls,
              float4*       __restrict__ out)
{
    int t    = threadIdx.x;
    int d4   = t & (D4 - 1);                    // 0..127
    int r0   = blockIdx.x * 8 + (t >> 7);       // rows r0 and r0+4
    const float4* embv = reinterpret_cast<const float4*>(g_emb);

#pragma unroll
    for (int rr = 0; rr < 2; rr++) {
        int row = r0 + rr * 4;
        int b   = row / LP1;
        int l   = row - b * LP1;
        int len = __ldg(&lengths[b]);

        float4 v;
        if (l < len) {
            float4 tk = __ldcs(&tok[(size_t)(b * LL + l) * D4 + d4]);
            float4 em = embv[l * D4 + d4];
            v.x = tk.x + em.x;
            v.y = tk.y + em.y;
            v.z = tk.z + em.z;
            v.w = tk.w + em.w;
        } else if (l == len) {
            v = __ldg(&cls[d4]);
        } else {
            v = make_float4(0.f, 0.f, 0.f, 0.f);
        }
        __stcs(&out[(size_t)row * D4 + d4], v);
    }
}

// ---------------------------------------------------------------------------
extern "C" void kernel_launch(void* const* d_in, const int* in_sizes, int n_in,
                              void* d_out, int out_size)
{
    const float4* tok     = (const float4*)d_in[0];   // tokens  [B,L,D] f32
    const int*    lengths = (const int*)   d_in[1];   // lengths [B]    i32
    const float4* cls     = (const float4*)d_in[2];   // cls     [D]    f32
    float4*       out     = (float4*)d_out;           // [B,L+1,D] f32

    compute_emb_kernel<<<LL / CH, DD>>>();

    int n_rows = BB * LP1;                  // 65552
    stream_kernel<<<n_rows / 8, 512>>>(tok, lengths, cls, out);
}